// round 1
// baseline (speedup 1.0000x reference)
#include <cuda_runtime.h>
#include <cuda_bf16.h>

// Problem constants
#define BB 8
#define CC 4
#define DD 128
#define HH 128
#define WW 128
#define FDIM 512
#define VOL (DD*HH*WW)          // 2097152 = 1<<21

// Per-batch rotation matrices computed on device (no allocations allowed)
__device__ float g_R[BB * 9];

// ---------------------------------------------------------------------------
// Kernel 1: per-batch mu/rho GEMV + rotation matrix build.
// grid = B blocks, 256 threads. Cost negligible.
// ---------------------------------------------------------------------------
__global__ void rot_kernel(const float* __restrict__ im_feat,
                           const float* __restrict__ pos_w,
                           const float* __restrict__ pos_b) {
    const int b = blockIdx.x;
    const int t = threadIdx.x;
    __shared__ float smu[256];
    __shared__ float srho[256];

    float pm = 0.f, pr = 0.f;
    for (int j = t; j < FDIM; j += 256) {
        float f = im_feat[b * FDIM + j];
        pm = fmaf(f, pos_w[j], pm);           // pos_w[0, j]
        pr = fmaf(f, pos_w[FDIM + j], pr);    // pos_w[1, j]
    }
    smu[t] = pm; srho[t] = pr;
    __syncthreads();
    for (int s = 128; s > 0; s >>= 1) {
        if (t < s) { smu[t] += smu[t + s]; srho[t] += srho[t + s]; }
        __syncthreads();
    }
    if (t == 0) {
        float mu  = smu[0]  + pos_b[0];
        float rho = srho[0] + pos_b[1];
        float cm = cosf(mu),  sm = sinf(mu);
        float cr = cosf(rho), sr = sinf(rho);
        // R = rot_y @ rot_x
        float* R = &g_R[b * 9];
        R[0] = cm;        R[1] = sm * sr;   R[2] = -sm * cr;
        R[3] = 0.f;       R[4] = cr;        R[5] = sr;
        R[6] = sm;        R[7] = -cm * sr;  R[8] = cm * cr;
    }
}

// ---------------------------------------------------------------------------
// Kernel 2: rotated trilinear grid_sample (align_corners=False, zero padding).
// One thread per spatial voxel; all 4 channels handled by the same thread so
// the index/weight math is amortized 4x. Writes are fully coalesced
// (w fastest). Gathers rely on L1/L2 corner reuse.
// grid = (VOL/256, B), block = 256.
// ---------------------------------------------------------------------------
__global__ void __launch_bounds__(256)
sample_kernel(const float* __restrict__ x, float* __restrict__ out) {
    const int b = blockIdx.y;

    __shared__ float R[9];
    if (threadIdx.x < 9) R[threadIdx.x] = g_R[b * 9 + threadIdx.x];
    __syncthreads();

    const int tid = blockIdx.x * 256 + threadIdx.x;   // < VOL
    const int w = tid & (WW - 1);
    const int h = (tid >> 7) & (HH - 1);
    const int d = tid >> 14;

    const float inv = 2.0f / 127.0f;
    const float X = fmaf((float)w, inv, -1.0f);
    const float Y = fmaf((float)h, inv, -1.0f);
    const float Z = fmaf((float)d, inv, -1.0f);

    const float gx = fmaf(R[0], X, fmaf(R[1], Y, R[2] * Z));
    const float gy = fmaf(R[4], Y, R[5] * Z);            // R[3] == 0
    const float gz = fmaf(R[6], X, fmaf(R[7], Y, R[8] * Z));

    // unnormalize (align_corners = False)
    const float ix = fmaf(gx + 1.0f, (float)WW * 0.5f, -0.5f);
    const float iy = fmaf(gy + 1.0f, (float)HH * 0.5f, -0.5f);
    const float iz = fmaf(gz + 1.0f, (float)DD * 0.5f, -0.5f);

    const float fxf = floorf(ix), fyf = floorf(iy), fzf = floorf(iz);
    const int ix0 = (int)fxf, iy0 = (int)fyf, iz0 = (int)fzf;
    const float fx = ix - fxf, fy = iy - fyf, fz = iz - fzf;

    // per-axis weights, zeroed when that plane is out of bounds (zero padding)
    const int x1 = ix0 + 1, y1 = iy0 + 1, z1 = iz0 + 1;
    float wx0 = (ix0 >= 0 && ix0 < WW) ? (1.0f - fx) : 0.0f;
    float wx1 = (x1  >= 0 && x1  < WW) ? fx          : 0.0f;
    float wy0 = (iy0 >= 0 && iy0 < HH) ? (1.0f - fy) : 0.0f;
    float wy1 = (y1  >= 0 && y1  < HH) ? fy          : 0.0f;
    float wz0 = (iz0 >= 0 && iz0 < DD) ? (1.0f - fz) : 0.0f;
    float wz1 = (z1  >= 0 && z1  < DD) ? fz          : 0.0f;

    // clamped indices (weight==0 makes the clamped read harmless)
    const int x0c = min(max(ix0, 0), WW - 1);
    const int x1c = min(max(x1,  0), WW - 1);
    const int y0c = min(max(iy0, 0), HH - 1);
    const int y1c = min(max(y1,  0), HH - 1);
    const int z0c = min(max(iz0, 0), DD - 1);
    const int z1c = min(max(z1,  0), DD - 1);

    const int zb0 = z0c * (HH * WW), zb1 = z1c * (HH * WW);
    const int yb0 = y0c * WW,        yb1 = y1c * WW;

    const int o00 = zb0 + yb0;   // + x gives corner offset
    const int o01 = zb0 + yb1;
    const int o10 = zb1 + yb0;
    const int o11 = zb1 + yb1;

    const float c00 = wz0 * wy0;
    const float c01 = wz0 * wy1;
    const float c10 = wz1 * wy0;
    const float c11 = wz1 * wy1;

    const long base_in  = ((long)(b * CC)) << 21;   // * VOL
    const long base_out = base_in + tid;

    #pragma unroll
    for (int c = 0; c < CC; ++c) {
        const float* p = x + base_in + ((long)c << 21);
        float a000 = __ldg(p + o00 + x0c);
        float a001 = __ldg(p + o00 + x1c);
        float a010 = __ldg(p + o01 + x0c);
        float a011 = __ldg(p + o01 + x1c);
        float a100 = __ldg(p + o10 + x0c);
        float a101 = __ldg(p + o10 + x1c);
        float a110 = __ldg(p + o11 + x0c);
        float a111 = __ldg(p + o11 + x1c);

        float v = c00 * fmaf(a000, wx0, a001 * wx1)
                + c01 * fmaf(a010, wx0, a011 * wx1)
                + c10 * fmaf(a100, wx0, a101 * wx1)
                + c11 * fmaf(a110, wx0, a111 * wx1);

        out[base_out + ((long)c << 21)] = v;
    }
}

extern "C" void kernel_launch(void* const* d_in, const int* in_sizes, int n_in,
                              void* d_out, int out_size) {
    const float* x       = (const float*)d_in[0];
    const float* im_feat = (const float*)d_in[1];
    const float* pos_w   = (const float*)d_in[2];
    const float* pos_b   = (const float*)d_in[3];
    float* out = (float*)d_out;

    rot_kernel<<<BB, 256>>>(im_feat, pos_w, pos_b);
    dim3 grid(VOL / 256, BB);
    sample_kernel<<<grid, 256>>>(x, out);
}

// round 2
// speedup vs baseline: 1.2532x; 1.2532x over previous
#include <cuda_runtime.h>
#include <cuda_bf16.h>

// Problem constants
#define BB 8
#define CC 4
#define DD 128
#define HH 128
#define WW 128
#define FDIM 512
#define VOL (DD*HH*WW)          // 2097152 = 1<<21

// Per-batch rotation matrices (computed on device; no allocations allowed)
__device__ float g_R[BB * 9];

// Channels-last scratch: [B, D, H, W, C] as float4 per voxel. 256 MiB static.
__device__ float4 g_xt[BB * VOL];

// ---------------------------------------------------------------------------
// Kernel 1: per-batch mu/rho GEMV + rotation matrix build. Negligible cost.
// ---------------------------------------------------------------------------
__global__ void rot_kernel(const float* __restrict__ im_feat,
                           const float* __restrict__ pos_w,
                           const float* __restrict__ pos_b) {
    const int b = blockIdx.x;
    const int t = threadIdx.x;
    __shared__ float smu[256];
    __shared__ float srho[256];

    float pm = 0.f, pr = 0.f;
    for (int j = t; j < FDIM; j += 256) {
        float f = im_feat[b * FDIM + j];
        pm = fmaf(f, pos_w[j], pm);           // pos_w[0, j]
        pr = fmaf(f, pos_w[FDIM + j], pr);    // pos_w[1, j]
    }
    smu[t] = pm; srho[t] = pr;
    __syncthreads();
    for (int s = 128; s > 0; s >>= 1) {
        if (t < s) { smu[t] += smu[t + s]; srho[t] += srho[t + s]; }
        __syncthreads();
    }
    if (t == 0) {
        float mu  = smu[0]  + pos_b[0];
        float rho = srho[0] + pos_b[1];
        float cm = cosf(mu),  sm = sinf(mu);
        float cr = cosf(rho), sr = sinf(rho);
        float* R = &g_R[b * 9];
        R[0] = cm;        R[1] = sm * sr;   R[2] = -sm * cr;
        R[3] = 0.f;       R[4] = cr;        R[5] = sr;
        R[6] = sm;        R[7] = -cm * sr;  R[8] = cm * cr;
    }
}

// ---------------------------------------------------------------------------
// Kernel 2: transpose [B,C,D,H,W] -> channels-last float4 scratch.
// Reads: 4 coalesced streams. Writes: STG.128 fully coalesced.
// ---------------------------------------------------------------------------
__global__ void __launch_bounds__(256)
transpose_kernel(const float* __restrict__ x) {
    const long tid = (long)blockIdx.x * 256 + threadIdx.x;   // < B*VOL
    const long b = tid >> 21;
    const long s = tid & (VOL - 1);
    const float* p = x + (b << 23) + s;                      // b * 4 * VOL
    float4 v;
    v.x = __ldg(p);
    v.y = __ldg(p + VOL);
    v.z = __ldg(p + 2 * VOL);
    v.w = __ldg(p + 3 * VOL);
    g_xt[tid] = v;
}

// ---------------------------------------------------------------------------
// Kernel 3: rotated trilinear grid_sample, gathering float4 (all 4 channels)
// per corner: 8x LDG.128 per thread instead of 32x LDG.32.
// grid = (VOL/256, B), block = 256.
// ---------------------------------------------------------------------------
__global__ void __launch_bounds__(256)
sample_kernel(float* __restrict__ out) {
    const int b = blockIdx.y;

    __shared__ float R[9];
    if (threadIdx.x < 9) R[threadIdx.x] = g_R[b * 9 + threadIdx.x];
    __syncthreads();

    const int tid = blockIdx.x * 256 + threadIdx.x;   // < VOL
    const int w = tid & (WW - 1);
    const int h = (tid >> 7) & (HH - 1);
    const int d = tid >> 14;

    const float inv = 2.0f / 127.0f;
    const float X = fmaf((float)w, inv, -1.0f);
    const float Y = fmaf((float)h, inv, -1.0f);
    const float Z = fmaf((float)d, inv, -1.0f);

    const float gx = fmaf(R[0], X, fmaf(R[1], Y, R[2] * Z));
    const float gy = fmaf(R[4], Y, R[5] * Z);            // R[3] == 0
    const float gz = fmaf(R[6], X, fmaf(R[7], Y, R[8] * Z));

    // unnormalize (align_corners = False)
    const float ix = fmaf(gx + 1.0f, (float)WW * 0.5f, -0.5f);
    const float iy = fmaf(gy + 1.0f, (float)HH * 0.5f, -0.5f);
    const float iz = fmaf(gz + 1.0f, (float)DD * 0.5f, -0.5f);

    const float fxf = floorf(ix), fyf = floorf(iy), fzf = floorf(iz);
    const int ix0 = (int)fxf, iy0 = (int)fyf, iz0 = (int)fzf;
    const float fx = ix - fxf, fy = iy - fyf, fz = iz - fzf;

    const int x1 = ix0 + 1, y1 = iy0 + 1, z1 = iz0 + 1;
    float wx0 = (ix0 >= 0 && ix0 < WW) ? (1.0f - fx) : 0.0f;
    float wx1 = (x1  >= 0 && x1  < WW) ? fx          : 0.0f;
    float wy0 = (iy0 >= 0 && iy0 < HH) ? (1.0f - fy) : 0.0f;
    float wy1 = (y1  >= 0 && y1  < HH) ? fy          : 0.0f;
    float wz0 = (iz0 >= 0 && iz0 < DD) ? (1.0f - fz) : 0.0f;
    float wz1 = (z1  >= 0 && z1  < DD) ? fz          : 0.0f;

    const int x0c = min(max(ix0, 0), WW - 1);
    const int x1c = min(max(x1,  0), WW - 1);
    const int y0c = min(max(iy0, 0), HH - 1);
    const int y1c = min(max(y1,  0), HH - 1);
    const int z0c = min(max(iz0, 0), DD - 1);
    const int z1c = min(max(z1,  0), DD - 1);

    const int zb0 = z0c * (HH * WW), zb1 = z1c * (HH * WW);
    const int yb0 = y0c * WW,        yb1 = y1c * WW;

    const int o00 = zb0 + yb0;
    const int o01 = zb0 + yb1;
    const int o10 = zb1 + yb0;
    const int o11 = zb1 + yb1;

    const float c00 = wz0 * wy0;
    const float c01 = wz0 * wy1;
    const float c10 = wz1 * wy0;
    const float c11 = wz1 * wy1;

    const float4* p = g_xt + ((long)b << 21);

    float4 a000 = __ldg(p + o00 + x0c);
    float4 a001 = __ldg(p + o00 + x1c);
    float4 a010 = __ldg(p + o01 + x0c);
    float4 a011 = __ldg(p + o01 + x1c);
    float4 a100 = __ldg(p + o10 + x0c);
    float4 a101 = __ldg(p + o10 + x1c);
    float4 a110 = __ldg(p + o11 + x0c);
    float4 a111 = __ldg(p + o11 + x1c);

    // acc = c00*(a000*wx0 + a001*wx1) + c01*(...) + ...
    float4 acc;
    acc.x = c00 * fmaf(a000.x, wx0, a001.x * wx1)
          + c01 * fmaf(a010.x, wx0, a011.x * wx1)
          + c10 * fmaf(a100.x, wx0, a101.x * wx1)
          + c11 * fmaf(a110.x, wx0, a111.x * wx1);
    acc.y = c00 * fmaf(a000.y, wx0, a001.y * wx1)
          + c01 * fmaf(a010.y, wx0, a011.y * wx1)
          + c10 * fmaf(a100.y, wx0, a101.y * wx1)
          + c11 * fmaf(a110.y, wx0, a111.y * wx1);
    acc.z = c00 * fmaf(a000.z, wx0, a001.z * wx1)
          + c01 * fmaf(a010.z, wx0, a011.z * wx1)
          + c10 * fmaf(a100.z, wx0, a101.z * wx1)
          + c11 * fmaf(a110.z, wx0, a111.z * wx1);
    acc.w = c00 * fmaf(a000.w, wx0, a001.w * wx1)
          + c01 * fmaf(a010.w, wx0, a011.w * wx1)
          + c10 * fmaf(a100.w, wx0, a101.w * wx1)
          + c11 * fmaf(a110.w, wx0, a111.w * wx1);

    const long base = ((long)(b * CC)) << 21;   // b*C*VOL
    out[base + tid]            = acc.x;
    out[base + VOL + tid]      = acc.y;
    out[base + 2L * VOL + tid] = acc.z;
    out[base + 3L * VOL + tid] = acc.w;
}

extern "C" void kernel_launch(void* const* d_in, const int* in_sizes, int n_in,
                              void* d_out, int out_size) {
    const float* x       = (const float*)d_in[0];
    const float* im_feat = (const float*)d_in[1];
    const float* pos_w   = (const float*)d_in[2];
    const float* pos_b   = (const float*)d_in[3];
    float* out = (float*)d_out;

    rot_kernel<<<BB, 256>>>(im_feat, pos_w, pos_b);
    transpose_kernel<<<BB * VOL / 256, 256>>>(x);
    dim3 grid(VOL / 256, BB);
    sample_kernel<<<grid, 256>>>(out);
}

// round 3
// speedup vs baseline: 1.5996x; 1.2764x over previous
#include <cuda_runtime.h>
#include <cuda_fp16.h>
#include <cuda_bf16.h>

// Problem constants
#define BB 8
#define CC 4
#define DD 128
#define HH 128
#define WW 128
#define FDIM 512
#define VOL (DD*HH*WW)          // 2097152 = 1<<21

// Per-batch rotation matrices (computed on device; no allocations allowed)
__device__ float g_R[BB * 9];

// Scratch: per voxel slot = {c0..c3 @ x, c0..c3 @ x+1} as 8 fp16 = 16 B.
// One LDG.128 fetches both x-corners for all 4 channels. 268 MiB static.
__device__ uint4 g_scr[(long)BB * VOL];

static __device__ __forceinline__ unsigned pack2(float a, float b) {
    __half2 h = __floats2half2_rn(a, b);
    return *reinterpret_cast<unsigned*>(&h);
}

// ---------------------------------------------------------------------------
// Kernel 1: prep. Block 0 additionally computes the 8 rotation matrices
// (warp-per-batch shuffle reduction). All blocks transpose their slice of
// [B,C,D,H,W] fp32 into the fp16 x-pair channels-last scratch.
// Thread handles 4 consecutive voxels. 1 thread : 4 slots.
// ---------------------------------------------------------------------------
__global__ void __launch_bounds__(256)
prep_kernel(const float* __restrict__ x,
            const float* __restrict__ im_feat,
            const float* __restrict__ pos_w,
            const float* __restrict__ pos_b) {
    if (blockIdx.x == 0) {
        const int wid = threadIdx.x >> 5;
        const int lane = threadIdx.x & 31;
        if (wid < BB) {
            float pm = 0.f, pr = 0.f;
            for (int j = lane; j < FDIM; j += 32) {
                float f = im_feat[wid * FDIM + j];
                pm = fmaf(f, pos_w[j], pm);
                pr = fmaf(f, pos_w[FDIM + j], pr);
            }
            #pragma unroll
            for (int s = 16; s; s >>= 1) {
                pm += __shfl_xor_sync(0xffffffffu, pm, s);
                pr += __shfl_xor_sync(0xffffffffu, pr, s);
            }
            if (lane == 0) {
                float mu  = pm + pos_b[0];
                float rho = pr + pos_b[1];
                float cm = cosf(mu),  sm = sinf(mu);
                float cr = cosf(rho), sr = sinf(rho);
                float* R = &g_R[wid * 9];
                R[0] = cm;        R[1] = sm * sr;   R[2] = -sm * cr;
                R[3] = 0.f;       R[4] = cr;        R[5] = sr;
                R[6] = sm;        R[7] = -cm * sr;  R[8] = cm * cr;
            }
        }
    }

    const long t = (long)blockIdx.x * 256 + threadIdx.x;  // < B*VOL/4
    const long s4 = t << 2;                               // first voxel (global)
    const long b = s4 >> 21;
    const long s = s4 & (VOL - 1);
    const float* base = x + (b << 23);                    // b*C*VOL

    float4 v0 = *(const float4*)(base + s);
    float4 v1 = *(const float4*)(base + VOL + s);
    float4 v2 = *(const float4*)(base + 2L * VOL + s);
    float4 v3 = *(const float4*)(base + 3L * VOL + s);
    const long sn = (s + 4 < VOL) ? (s + 4) : (VOL - 1);  // clamp: value unused (weight 0)
    float a0[5] = {v0.x, v0.y, v0.z, v0.w, base[sn]};
    float a1[5] = {v1.x, v1.y, v1.z, v1.w, base[VOL + sn]};
    float a2[5] = {v2.x, v2.y, v2.z, v2.w, base[2L * VOL + sn]};
    float a3[5] = {v3.x, v3.y, v3.z, v3.w, base[3L * VOL + sn]};

    uint4* dst = g_scr + s4;
    #pragma unroll
    for (int j = 0; j < 4; ++j) {
        uint4 slot;
        slot.x = pack2(a0[j],     a1[j]);
        slot.y = pack2(a2[j],     a3[j]);
        slot.z = pack2(a0[j + 1], a1[j + 1]);
        slot.w = pack2(a2[j + 1], a3[j + 1]);
        dst[j] = slot;
    }
}

// ---------------------------------------------------------------------------
// Kernel 2: rotated trilinear grid_sample. 4 LDG.128 per voxel (each load
// covers both x-corners x all 4 channels). grid = (VOL/256, B), block 256.
// ---------------------------------------------------------------------------
__global__ void __launch_bounds__(256)
sample_kernel(float* __restrict__ out) {
    const int b = blockIdx.y;

    __shared__ float R[9];
    if (threadIdx.x < 9) R[threadIdx.x] = g_R[b * 9 + threadIdx.x];
    __syncthreads();

    const int tid = blockIdx.x * 256 + threadIdx.x;   // < VOL
    const int w = tid & (WW - 1);
    const int h = (tid >> 7) & (HH - 1);
    const int d = tid >> 14;

    const float inv = 2.0f / 127.0f;
    const float X = fmaf((float)w, inv, -1.0f);
    const float Y = fmaf((float)h, inv, -1.0f);
    const float Z = fmaf((float)d, inv, -1.0f);

    const float gx = fmaf(R[0], X, fmaf(R[1], Y, R[2] * Z));
    const float gy = fmaf(R[4], Y, R[5] * Z);            // R[3] == 0
    const float gz = fmaf(R[6], X, fmaf(R[7], Y, R[8] * Z));

    // unnormalize (align_corners = False)
    const float ix = fmaf(gx + 1.0f, (float)WW * 0.5f, -0.5f);
    const float iy = fmaf(gy + 1.0f, (float)HH * 0.5f, -0.5f);
    const float iz = fmaf(gz + 1.0f, (float)DD * 0.5f, -0.5f);

    const float fxf = floorf(ix), fyf = floorf(iy), fzf = floorf(iz);
    const int ix0 = (int)fxf, iy0 = (int)fyf, iz0 = (int)fzf;
    const float fx = ix - fxf, fy = iy - fyf, fz = iz - fzf;

    const int x1 = ix0 + 1, y1 = iy0 + 1, z1 = iz0 + 1;
    const float wx0 = (ix0 >= 0 && ix0 < WW) ? (1.0f - fx) : 0.0f;
    const float wx1 = (x1  >= 0 && x1  < WW) ? fx          : 0.0f;
    const float wy0 = (iy0 >= 0 && iy0 < HH) ? (1.0f - fy) : 0.0f;
    const float wy1 = (y1  >= 0 && y1  < HH) ? fy          : 0.0f;
    const float wz0 = (iz0 >= 0 && iz0 < DD) ? (1.0f - fz) : 0.0f;
    const float wz1 = (z1  >= 0 && z1  < DD) ? fz          : 0.0f;

    // Slot index + remapped pair weights (slot s covers x = s and s+1).
    const int xs = min(max(ix0, 0), WW - 1);
    const float wA = (ix0 >= 0) ? wx0 : wx1;   // weight for slot's first voxel
    const float wB = (ix0 >= 0) ? wx1 : 0.0f;  // weight for slot's second voxel

    const int y0c = min(max(iy0, 0), HH - 1);
    const int y1c = min(max(y1,  0), HH - 1);
    const int z0c = min(max(iz0, 0), DD - 1);
    const int z1c = min(max(z1,  0), DD - 1);

    const int zb0 = z0c * (HH * WW), zb1 = z1c * (HH * WW);
    const int yb0 = y0c * WW,        yb1 = y1c * WW;

    const int o00 = zb0 + yb0 + xs;
    const int o01 = zb0 + yb1 + xs;
    const int o10 = zb1 + yb0 + xs;
    const int o11 = zb1 + yb1 + xs;

    const float c00 = wz0 * wy0;
    const float c01 = wz0 * wy1;
    const float c10 = wz1 * wy0;
    const float c11 = wz1 * wy1;

    const uint4* p = g_scr + ((long)b << 21);

    const uint4 g00 = __ldg(p + o00);
    const uint4 g01 = __ldg(p + o01);
    const uint4 g10 = __ldg(p + o10);
    const uint4 g11 = __ldg(p + o11);

    float acc0 = 0.f, acc1 = 0.f, acc2 = 0.f, acc3 = 0.f;

    #define ACC_CORNER(g, cw)                                                   \
    {                                                                           \
        float2 lo01 = __half22float2(*reinterpret_cast<const __half2*>(&g.x));  \
        float2 lo23 = __half22float2(*reinterpret_cast<const __half2*>(&g.y));  \
        float2 hi01 = __half22float2(*reinterpret_cast<const __half2*>(&g.z));  \
        float2 hi23 = __half22float2(*reinterpret_cast<const __half2*>(&g.w));  \
        acc0 = fmaf(cw, fmaf(wA, lo01.x, wB * hi01.x), acc0);                   \
        acc1 = fmaf(cw, fmaf(wA, lo01.y, wB * hi01.y), acc1);                   \
        acc2 = fmaf(cw, fmaf(wA, lo23.x, wB * hi23.x), acc2);                   \
        acc3 = fmaf(cw, fmaf(wA, lo23.y, wB * hi23.y), acc3);                   \
    }

    ACC_CORNER(g00, c00)
    ACC_CORNER(g01, c01)
    ACC_CORNER(g10, c10)
    ACC_CORNER(g11, c11)

    const long base = ((long)(b * CC)) << 21;   // b*C*VOL
    out[base + tid]            = acc0;
    out[base + VOL + tid]      = acc1;
    out[base + 2L * VOL + tid] = acc2;
    out[base + 3L * VOL + tid] = acc3;
}

extern "C" void kernel_launch(void* const* d_in, const int* in_sizes, int n_in,
                              void* d_out, int out_size) {
    const float* x       = (const float*)d_in[0];
    const float* im_feat = (const float*)d_in[1];
    const float* pos_w   = (const float*)d_in[2];
    const float* pos_b   = (const float*)d_in[3];
    float* out = (float*)d_out;

    prep_kernel<<<BB * VOL / 4 / 256, 256>>>(x, im_feat, pos_w, pos_b);
    dim3 grid(VOL / 256, BB);
    sample_kernel<<<grid, 256>>>(out);
}